// round 3
// baseline (speedup 1.0000x reference)
#include <cuda_runtime.h>

// ---------------------------------------------------------------------------
// MultiScaleRoIAlign (torchvision, aligned=False, SR=2) — single kernel,
// gathers directly from NCHW via per-ROI smem feature windows.
//
// Window-size bound: level mapper guarantees scaled roi area <= ~784 px^2
// (lvl0 worst case incl. extreme aspect ratios gives hr*ws <= ~1300 floats).
// WIN_STRIDE = 1409 (odd per-channel stride -> bank-friendly) is a safe cap.
//
// grid = (512 rois, 4 channel-slices of 64); block = 256 threads.
// Per 8-channel chunk: warp w stages channel w's window (coalesced row loads),
// then 392 items (c*49+bin) compute bilinear from smem; stores are contiguous.
// ---------------------------------------------------------------------------

#define WIN_STRIDE 1409

__global__ void __launch_bounds__(256)
msroi_kernel(const float* __restrict__ f0, const float* __restrict__ f1,
             const float* __restrict__ f2, const float* __restrict__ f3,
             const float* __restrict__ boxes, float* __restrict__ out)
{
    __shared__ float win[8][WIN_STRIDE];
    __shared__ float s_hy[14], s_ly[14], s_hx[14], s_lx[14];
    __shared__ int   s_yl[14], s_yh[14], s_xl[14], s_xh[14];

    const int tid = threadIdx.x;
    const int n = blockIdx.x;                 // roi 0..511
    const int b = n >> 8;                     // batch

    float4 bx = __ldg(reinterpret_cast<const float4*>(boxes) + n);

    // LevelMapper: floor(4 + log2(sqrt(w*h)/224) + 1e-6), clip [2,5], -2
    float s = sqrtf((bx.z - bx.x) * (bx.w - bx.y));
    int lvl = (int)floorf(4.0f + log2f(s * (1.0f / 224.0f)) + 1e-6f);
    lvl = min(max(lvl, 2), 5) - 2;

    int H; float sc; const float* base;
    switch (lvl) {
        case 0:  H = 200; sc = 0.25f;    base = f0; break;
        case 1:  H = 100; sc = 0.125f;   base = f1; break;
        case 2:  H = 50;  sc = 0.0625f;  base = f2; break;
        default: H = 25;  sc = 0.03125f; base = f3; break;
    }
    const int HH = H * H;
    base += (size_t)b * 256 * HH;

    float x1s = bx.x * sc, y1s = bx.y * sc;
    float x2s = bx.z * sc, y2s = bx.w * sc;
    float binw = fmaxf(x2s - x1s, 1.0f) * (1.0f / 7.0f);
    float binh = fmaxf(y2s - y1s, 1.0f) * (1.0f / 7.0f);
    float fH = (float)H;

    // window bounds (covers all clipped sample taps)
    float ymin = y1s + 0.25f * binh, ymax = y1s + 6.75f * binh;
    float xmin = x1s + 0.25f * binw, xmax = x1s + 6.75f * binw;
    int y0  = min((int)fmaxf(ymin, 0.0f), H - 1);
    int x0  = min((int)fmaxf(xmin, 0.0f), H - 1);
    int y1m = min((int)fmaxf(fminf(ymax, fH - 1.0f), 0.0f) + 1, H - 1);
    int x1m = min((int)fmaxf(fminf(xmax, fH - 1.0f), 0.0f) + 1, H - 1);
    int hr = y1m - y0 + 1;
    int wc = x1m - x0 + 1;
    int ws = wc | 1;                          // odd stride

    // per-sample bilinear params (14 y-samples, 14 x-samples)
    if (tid < 28) {
        bool isY = tid < 14;
        int j = isY ? tid : tid - 14;
        float o = (float)(j >> 1) + 0.25f + 0.5f * (float)(j & 1);
        float v = isY ? (y1s + o * binh) : (x1s + o * binw);
        bool valid = (v > -1.0f) && (v < fH);
        float vc = fmaxf(v, 0.0f);
        int lo = min((int)vc, H - 1);
        int hi = min(lo + 1, H - 1);
        float l = (lo >= H - 1) ? 0.0f : (vc - (float)lo);
        float h = 1.0f - l;
        if (!valid) { l = 0.0f; h = 0.0f; lo = isY ? y0 : x0; hi = lo; }
        if (isY) { s_yl[j] = lo - y0; s_yh[j] = hi - y0; s_ly[j] = l; s_hy[j] = h; }
        else     { s_xl[j] = lo - x0; s_xh[j] = hi - x0; s_lx[j] = l; s_hx[j] = h; }
    }
    __syncthreads();

    const int warp = tid >> 5, lane = tid & 31;
    const int cbase = blockIdx.y * 64;        // 64 channels per y-slice

    #pragma unroll 1
    for (int cc = 0; cc < 8; cc++) {
        int c0 = cbase + cc * 8;

        // warp w stages channel (c0+w)'s window; lanes along x (coalesced)
        {
            const float* pl = base + (size_t)(c0 + warp) * HH + y0 * H + x0;
            for (int r = 0; r < hr; r++)
                for (int cx = lane; cx < wc; cx += 32) {
                    int si = r * ws + cx;
                    if (si < WIN_STRIDE) win[warp][si] = pl[r * H + cx];
                }
        }
        __syncthreads();

        float* on = out + (size_t)n * 12544 + c0 * 49;
        #pragma unroll 1
        for (int item = tid; item < 392; item += 256) {
            int c   = item / 49;
            int bin = item - c * 49;
            int oy  = bin / 7;
            int ox  = bin - oy * 7;
            float acc = 0.0f;
            #pragma unroll
            for (int sy = 0; sy < 2; sy++) {
                int j = oy * 2 + sy;
                float hy = s_hy[j], ly = s_ly[j];
                int r0 = s_yl[j] * ws, r1 = s_yh[j] * ws;
                #pragma unroll
                for (int sx = 0; sx < 2; sx++) {
                    int k = ox * 2 + sx;
                    float hx = s_hx[k], lx = s_lx[k];
                    int xl = s_xl[k], xh = s_xh[k];
                    acc += hy * (hx * win[c][r0 + xl] + lx * win[c][r0 + xh])
                         + ly * (hx * win[c][r1 + xl] + lx * win[c][r1 + xh]);
                }
            }
            on[item] = acc * 0.25f;           // contiguous store across lanes
        }
        __syncthreads();
    }
}

extern "C" void kernel_launch(void* const* d_in, const int* in_sizes, int n_in,
                              void* d_out, int out_size)
{
    const float* f0 = (const float*)d_in[0];
    const float* f1 = (const float*)d_in[1];
    const float* f2 = (const float*)d_in[2];
    const float* f3 = (const float*)d_in[3];
    const float* boxes = (const float*)d_in[4];
    float* out = (float*)d_out;

    msroi_kernel<<<dim3(512, 4), 256>>>(f0, f1, f2, f3, boxes, out);
}

// round 4
// speedup vs baseline: 3.1528x; 3.1528x over previous
#include <cuda_runtime.h>

// ---------------------------------------------------------------------------
// MultiScaleRoIAlign (torchvision, aligned=False, SR=2) — single kernel,
// gathers directly from NCHW via per-ROI smem feature windows.
//
// Window bound (from FPN level mapper, s in [224*2^(k-2), 224*2^(k-1)) for
// assigned level k, box sides <= 588 px): hr*ws <= ~1341 < 1409.
//
// grid = (512 rois, 4 channel-slices of 64); block = 256 threads (8 warps).
// Per 8-channel chunk: warp w stages channel w's window with a 2D lane map
// (lanes cover 32/wp2 rows x wp2 cols) + 4-row manual unroll => MLP>=4.
// Then 392 items (c*49+bin) compute bilinear from smem; stores contiguous.
// ---------------------------------------------------------------------------

#define WIN_STRIDE 1409

__global__ void __launch_bounds__(256)
msroi_kernel(const float* __restrict__ f0, const float* __restrict__ f1,
             const float* __restrict__ f2, const float* __restrict__ f3,
             const float* __restrict__ boxes, float* __restrict__ out)
{
    __shared__ float win[8][WIN_STRIDE];
    __shared__ float s_hy[14], s_ly[14], s_hx[14], s_lx[14];
    __shared__ int   s_yl[14], s_yh[14], s_xl[14], s_xh[14];

    const int tid = threadIdx.x;
    const int n = blockIdx.x;                 // roi 0..511
    const int b = n >> 8;                     // batch

    float4 bx = __ldg(reinterpret_cast<const float4*>(boxes) + n);

    // LevelMapper: floor(4 + log2(sqrt(w*h)/224) + 1e-6), clip [2,5], -2
    float s = sqrtf((bx.z - bx.x) * (bx.w - bx.y));
    int lvl = (int)floorf(4.0f + log2f(s * (1.0f / 224.0f)) + 1e-6f);
    lvl = min(max(lvl, 2), 5) - 2;

    int H; float sc; const float* base;
    switch (lvl) {
        case 0:  H = 200; sc = 0.25f;    base = f0; break;
        case 1:  H = 100; sc = 0.125f;   base = f1; break;
        case 2:  H = 50;  sc = 0.0625f;  base = f2; break;
        default: H = 25;  sc = 0.03125f; base = f3; break;
    }
    const int HH = H * H;
    base += (size_t)b * 256 * HH;

    float x1s = bx.x * sc, y1s = bx.y * sc;
    float x2s = bx.z * sc, y2s = bx.w * sc;
    float binw = fmaxf(x2s - x1s, 1.0f) * (1.0f / 7.0f);
    float binh = fmaxf(y2s - y1s, 1.0f) * (1.0f / 7.0f);
    float fH = (float)H;

    // window bounds (covers all clipped sample taps)
    float ymin = y1s + 0.25f * binh, ymax = y1s + 6.75f * binh;
    float xmin = x1s + 0.25f * binw, xmax = x1s + 6.75f * binw;
    int y0  = min((int)fmaxf(ymin, 0.0f), H - 1);
    int x0  = min((int)fmaxf(xmin, 0.0f), H - 1);
    int y1m = min((int)fmaxf(fminf(ymax, fH - 1.0f), 0.0f) + 1, H - 1);
    int x1m = min((int)fmaxf(fminf(xmax, fH - 1.0f), 0.0f) + 1, H - 1);
    int hr = y1m - y0 + 1;
    int wc = x1m - x0 + 1;
    int ws = wc | 1;                          // odd smem row stride

    // per-sample bilinear params (14 y-samples, 14 x-samples)
    if (tid < 28) {
        bool isY = tid < 14;
        int j = isY ? tid : tid - 14;
        float o = (float)(j >> 1) + 0.25f + 0.5f * (float)(j & 1);
        float v = isY ? (y1s + o * binh) : (x1s + o * binw);
        bool valid = (v > -1.0f) && (v < fH);
        float vc = fmaxf(v, 0.0f);
        int lo = min((int)vc, H - 1);
        int hi = min(lo + 1, H - 1);
        float l = (lo >= H - 1) ? 0.0f : (vc - (float)lo);
        float h = 1.0f - l;
        if (!valid) { l = 0.0f; h = 0.0f; lo = isY ? y0 : x0; hi = lo; }
        if (isY) { s_yl[j] = lo - y0; s_yh[j] = hi - y0; s_ly[j] = l; s_hy[j] = h; }
        else     { s_xl[j] = lo - x0; s_xh[j] = hi - x0; s_lx[j] = l; s_hx[j] = h; }
    }

    // 2D lane map for staging: wp2 = pow2 >= wc (capped 32)
    int wp2 = 1;
    while (wp2 < wc && wp2 < 32) wp2 <<= 1;
    const int shift = __popc(wp2 - 1);        // log2(wp2)
    const int rpw = 32 >> shift;              // rows covered per warp step

    const int warp = tid >> 5, lane = tid & 31;
    const int lx  = lane & (wp2 - 1);
    const int lr0 = lane >> shift;
    const int cbase = blockIdx.y * 64;        // 64 channels per y-slice

    __syncthreads();

    #pragma unroll 1
    for (int cc = 0; cc < 8; cc++) {
        int c0 = cbase + cc * 8;

        // ---- stage channel (c0+warp)'s window, MLP-4 ----
        {
            const float* pl = base + (size_t)(c0 + warp) * HH + y0 * H + x0;
            #pragma unroll 1
            for (int cx0 = 0; cx0 < wc; cx0 += wp2) {
                int xx = cx0 + lx;
                bool inx = xx < wc;
                #pragma unroll 1
                for (int r0 = 0; r0 < hr; r0 += rpw * 4) {
                    int ra = r0 + lr0;
                    int rb = ra + rpw, rc = ra + 2 * rpw, rd = ra + 3 * rpw;
                    bool ba = inx && ra < hr;
                    bool bb = inx && rb < hr;
                    bool bc = inx && rc < hr;
                    bool bd = inx && rd < hr;
                    float va = 0.f, vb = 0.f, vcv = 0.f, vd = 0.f;
                    if (ba) va  = pl[ra * H + xx];
                    if (bb) vb  = pl[rb * H + xx];
                    if (bc) vcv = pl[rc * H + xx];
                    if (bd) vd  = pl[rd * H + xx];
                    int sa = ra * ws + xx, sb = rb * ws + xx;
                    int scn = rc * ws + xx, sd = rd * ws + xx;
                    if (ba && sa < WIN_STRIDE) win[warp][sa]  = va;
                    if (bb && sb < WIN_STRIDE) win[warp][sb]  = vb;
                    if (bc && scn < WIN_STRIDE) win[warp][scn] = vcv;
                    if (bd && sd < WIN_STRIDE) win[warp][sd]  = vd;
                }
            }
        }
        __syncthreads();

        // ---- compute 8 channels x 49 bins ----
        float* on = out + (size_t)n * 12544 + c0 * 49;
        #pragma unroll 1
        for (int item = tid; item < 392; item += 256) {
            int c   = item / 49;
            int bin = item - c * 49;
            int oy  = bin / 7;
            int ox  = bin - oy * 7;
            float acc = 0.0f;
            #pragma unroll
            for (int sy = 0; sy < 2; sy++) {
                int j = oy * 2 + sy;
                float hy = s_hy[j], ly = s_ly[j];
                int r0 = s_yl[j] * ws, r1 = s_yh[j] * ws;
                #pragma unroll
                for (int sx = 0; sx < 2; sx++) {
                    int k = ox * 2 + sx;
                    float hx = s_hx[k], lxw = s_lx[k];
                    int xl = s_xl[k], xh = s_xh[k];
                    acc += hy * (hx * win[c][r0 + xl] + lxw * win[c][r0 + xh])
                         + ly * (hx * win[c][r1 + xl] + lxw * win[c][r1 + xh]);
                }
            }
            on[item] = acc * 0.25f;           // contiguous store across lanes
        }
        __syncthreads();
    }
}

extern "C" void kernel_launch(void* const* d_in, const int* in_sizes, int n_in,
                              void* d_out, int out_size)
{
    const float* f0 = (const float*)d_in[0];
    const float* f1 = (const float*)d_in[1];
    const float* f2 = (const float*)d_in[2];
    const float* f3 = (const float*)d_in[3];
    const float* boxes = (const float*)d_in[4];
    float* out = (float*)d_out;

    msroi_kernel<<<dim3(512, 4), 256>>>(f0, f1, f2, f3, boxes, out);
}

// round 5
// speedup vs baseline: 3.2182x; 1.0207x over previous
#include <cuda_runtime.h>

// ---------------------------------------------------------------------------
// MultiScaleRoIAlign (torchvision, aligned=False, SR=2) — single kernel.
// grid=(512 rois, 4 slices of 64 ch), block=256.
// 16 chunks of 4 channels; per chunk: 8 warps stage 4 channel windows
// (float2, 2 warps/channel, double-buffered) while 196 threads compute one
// (channel,bin) output each from registers-precomputed bilinear params.
// Window bound: hr * rs2 <= 768 float2 per channel (level mapper: s_scaled<28).
// ---------------------------------------------------------------------------

#define WS2 768   // float2 slots per channel window

__global__ void __launch_bounds__(256, 4)
msroi_kernel(const float* __restrict__ f0, const float* __restrict__ f1,
             const float* __restrict__ f2, const float* __restrict__ f3,
             const float* __restrict__ boxes, float* __restrict__ out)
{
    __shared__ float2 win[2][4][WS2];
    __shared__ float s_hy[14], s_ly[14], s_hx[14], s_lx[14];
    __shared__ int   s_yl[14], s_yh[14], s_xl[14], s_xh[14];

    const int tid = threadIdx.x;
    const int n = blockIdx.x;
    const int b = n >> 8;

    float4 bx = __ldg(reinterpret_cast<const float4*>(boxes) + n);

    // LevelMapper: floor(4 + log2(sqrt(w*h)/224) + 1e-6), clip [2,5], -2
    float s = sqrtf((bx.z - bx.x) * (bx.w - bx.y));
    int lvl = (int)floorf(4.0f + log2f(s * (1.0f / 224.0f)) + 1e-6f);
    lvl = min(max(lvl, 2), 5) - 2;

    int H; float sc; const float* base;
    switch (lvl) {
        case 0:  H = 200; sc = 0.25f;    base = f0; break;
        case 1:  H = 100; sc = 0.125f;   base = f1; break;
        case 2:  H = 50;  sc = 0.0625f;  base = f2; break;
        default: H = 25;  sc = 0.03125f; base = f3; break;
    }
    const int HH = H * H;
    base += (size_t)b * 256 * HH;

    float x1s = bx.x * sc, y1s = bx.y * sc;
    float x2s = bx.z * sc, y2s = bx.w * sc;
    float binw = fmaxf(x2s - x1s, 1.0f) * (1.0f / 7.0f);
    float binh = fmaxf(y2s - y1s, 1.0f) * (1.0f / 7.0f);
    float fH = (float)H;

    // window bounds
    float ymin = y1s + 0.25f * binh, ymax = y1s + 6.75f * binh;
    float xmin = x1s + 0.25f * binw, xmax = x1s + 6.75f * binw;
    int y0  = min((int)fmaxf(ymin, 0.0f), H - 1);
    int x0  = min((int)fmaxf(xmin, 0.0f), H - 1);
    int y1m = min((int)fmaxf(fminf(ymax, fH - 1.0f), 0.0f) + 1, H - 1);
    int x1m = min((int)fmaxf(fminf(xmax, fH - 1.0f), 0.0f) + 1, H - 1);
    int hr  = y1m - y0 + 1;
    int x0d = x0 & ~1;                         // float2-aligned window start
    int wc2 = (x1m >> 1) - (x0d >> 1) + 1;     // float2 per row
    int rs2 = wc2 | 1;                         // odd float2 row stride
    const int rsF = rs2 * 2;                   // float row stride

    // per-sample bilinear params (14 y, 14 x)
    if (tid < 28) {
        bool isY = tid < 14;
        int j = isY ? tid : tid - 14;
        float o = (float)(j >> 1) + 0.25f + 0.5f * (float)(j & 1);
        float v = isY ? (y1s + o * binh) : (x1s + o * binw);
        bool valid = (v > -1.0f) && (v < fH);
        float vc = fmaxf(v, 0.0f);
        int lo = min((int)vc, H - 1);
        int hi = min(lo + 1, H - 1);
        float l = (lo >= H - 1) ? 0.0f : (vc - (float)lo);
        float h = 1.0f - l;
        if (!valid) { l = 0.0f; h = 0.0f; lo = isY ? y0 : x0d; hi = lo; }
        if (isY) { s_yl[j] = lo - y0;  s_yh[j] = hi - y0;  s_ly[j] = l; s_hy[j] = h; }
        else     { s_xl[j] = lo - x0d; s_xh[j] = hi - x0d; s_lx[j] = l; s_hx[j] = h; }
    }
    __syncthreads();

    // ---- per-thread compute params in registers (tid < 196) ----
    int cidx = 0, r0a = 0, r1a = 0, r0b = 0, r1b = 0, xl0 = 0, xh0 = 0, xl1 = 0, xh1 = 0;
    float hy0 = 0, ly0 = 0, hy1 = 0, ly1 = 0, hx0 = 0, lx0 = 0, hx1 = 0, lx1 = 0;
    if (tid < 196) {
        cidx = tid / 49;
        int bin = tid - cidx * 49;
        int oy = bin / 7, ox = bin - oy * 7;
        int j0 = oy * 2, j1 = j0 + 1, k0 = ox * 2, k1 = k0 + 1;
        r0a = s_yl[j0] * rsF; r1a = s_yh[j0] * rsF;
        r0b = s_yl[j1] * rsF; r1b = s_yh[j1] * rsF;
        xl0 = s_xl[k0]; xh0 = s_xh[k0]; xl1 = s_xl[k1]; xh1 = s_xh[k1];
        hy0 = s_hy[j0]; ly0 = s_ly[j0]; hy1 = s_hy[j1]; ly1 = s_ly[j1];
        hx0 = s_hx[k0]; lx0 = s_lx[k0]; hx1 = s_hx[k1]; lx1 = s_lx[k1];
    }
    float* outp = out + (size_t)n * 12544 + blockIdx.y * (64 * 49) + tid;

    // ---- staging lane geometry ----
    const int warp = tid >> 5, lane = tid & 31;
    const int cw = warp & 3, half = warp >> 2;   // 2 warps per channel
    const int cbase = blockIdx.y * 64;
    const bool h25 = (H == 25);
    const int wide = h25 ? (wc2 * 2) : wc2;      // elements per row (f32 / f2)
    int wp2 = 1;
    while (wp2 < wide && wp2 < 32) wp2 <<= 1;
    const int shift = __popc(wp2 - 1);
    const int rpw = 32 >> shift;                 // rows per warp step
    const int lxe = lane & (wp2 - 1);
    const int lr0 = lane >> shift;
    const int H2 = H >> 1;
    const int xlim = x1m - x0d;                  // scalar-path x predicate

    // stage chunk ck's 4 channels into buffer bf (this thread handles channel cw)
    auto stage = [&](int bf, int ck) {
        const int cglob = cbase + ck * 4 + cw;
        if (!h25) {
            const float2* src = reinterpret_cast<const float2*>(base)
                              + (size_t)cglob * (HH >> 1) + y0 * H2 + (x0d >> 1);
            float2* wp = win[bf][cw];
            for (int cx0 = 0; cx0 < wc2; cx0 += wp2) {
                int xx = cx0 + lxe;
                bool inx = xx < wc2;
                for (int rb0 = half * 2 * rpw; rb0 < hr; rb0 += 4 * rpw) {
                    int ra = rb0 + lr0, rb = ra + rpw;
                    bool pa = inx && ra < hr, pb = inx && rb < hr;
                    float2 va = make_float2(0.f, 0.f), vb = va;
                    if (pa) va = __ldg(src + ra * H2 + xx);
                    if (pb) vb = __ldg(src + rb * H2 + xx);
                    if (pa) wp[ra * rs2 + xx] = va;
                    if (pb) wp[rb * rs2 + xx] = vb;
                }
            }
        } else {
            const float* src = base + (size_t)cglob * HH + y0 * H + x0d;
            float* wp = reinterpret_cast<float*>(win[bf][cw]);
            for (int cx0 = 0; cx0 < wide; cx0 += wp2) {
                int xx = cx0 + lxe;
                bool inx = xx <= xlim;
                for (int rb0 = half * 2 * rpw; rb0 < hr; rb0 += 4 * rpw) {
                    int ra = rb0 + lr0, rb = ra + rpw;
                    bool pa = inx && ra < hr, pb = inx && rb < hr;
                    float va = 0.f, vb = 0.f;
                    if (pa) va = __ldg(src + ra * H + xx);
                    if (pb) vb = __ldg(src + rb * H + xx);
                    if (pa) wp[ra * rsF + xx] = va;
                    if (pb) wp[rb * rsF + xx] = vb;
                }
            }
        }
    };

    stage(0, 0);
    __syncthreads();

    #pragma unroll 1
    for (int ck = 0; ck < 16; ck++) {
        int bf = ck & 1;
        if (ck < 15) stage(bf ^ 1, ck + 1);

        if (tid < 196) {
            const float* W = reinterpret_cast<const float*>(win[bf][cidx]);
            float acc =
                  hy0 * (hx0 * W[r0a + xl0] + lx0 * W[r0a + xh0])
                + ly0 * (hx0 * W[r1a + xl0] + lx0 * W[r1a + xh0])
                + hy0 * (hx1 * W[r0a + xl1] + lx1 * W[r0a + xh1])
                + ly0 * (hx1 * W[r1a + xl1] + lx1 * W[r1a + xh1])
                + hy1 * (hx0 * W[r0b + xl0] + lx0 * W[r0b + xh0])
                + ly1 * (hx0 * W[r1b + xl0] + lx0 * W[r1b + xh0])
                + hy1 * (hx1 * W[r0b + xl1] + lx1 * W[r0b + xh1])
                + ly1 * (hx1 * W[r1b + xl1] + lx1 * W[r1b + xh1]);
            outp[ck * 196] = acc * 0.25f;
        }
        __syncthreads();
    }
}

extern "C" void kernel_launch(void* const* d_in, const int* in_sizes, int n_in,
                              void* d_out, int out_size)
{
    const float* f0 = (const float*)d_in[0];
    const float* f1 = (const float*)d_in[1];
    const float* f2 = (const float*)d_in[2];
    const float* f3 = (const float*)d_in[3];
    const float* boxes = (const float*)d_in[4];
    float* out = (float*)d_out;

    msroi_kernel<<<dim3(512, 4), 256>>>(f0, f1, f2, f3, boxes, out);
}

// round 6
// speedup vs baseline: 4.1747x; 1.2972x over previous
#include <cuda_runtime.h>
#include <cstdint>

// ---------------------------------------------------------------------------
// MultiScaleRoIAlign (torchvision, aligned=False, SR=2) — single kernel.
// grid=(512 rois, 4 slices of 64 ch), block=256.
// 16 chunks of 4 channels; staging now uses cp.async (LDGSTS) so window
// copies issue without LDG->STS register dependency; double-buffered with
// commit_group/wait_group. Compute: 196 threads, one (channel,bin) output
// each, bilinear params precomputed in registers.
// Window bound: hr * rs2 <= 768 float2 per channel (level mapper: s_scaled<28).
// ---------------------------------------------------------------------------

#define WS2 768   // float2 slots per channel window

__device__ __forceinline__ void cp_async8(uint32_t dst, const void* src, bool p)
{
    if (p) asm volatile("cp.async.ca.shared.global [%0], [%1], 8;"
                        :: "r"(dst), "l"(src) : "memory");
}
__device__ __forceinline__ void cp_async4(uint32_t dst, const void* src, bool p)
{
    if (p) asm volatile("cp.async.ca.shared.global [%0], [%1], 4;"
                        :: "r"(dst), "l"(src) : "memory");
}
#define CP_COMMIT()  asm volatile("cp.async.commit_group;" ::: "memory")
#define CP_WAIT(N)   asm volatile("cp.async.wait_group %0;" :: "n"(N) : "memory")

__global__ void __launch_bounds__(256, 4)
msroi_kernel(const float* __restrict__ f0, const float* __restrict__ f1,
             const float* __restrict__ f2, const float* __restrict__ f3,
             const float* __restrict__ boxes, float* __restrict__ out)
{
    __shared__ float2 win[2][4][WS2];
    __shared__ float s_hy[14], s_ly[14], s_hx[14], s_lx[14];
    __shared__ int   s_yl[14], s_yh[14], s_xl[14], s_xh[14];

    const int tid = threadIdx.x;
    const int n = blockIdx.x;
    const int b = n >> 8;

    float4 bx = __ldg(reinterpret_cast<const float4*>(boxes) + n);

    // LevelMapper: floor(4 + log2(sqrt(w*h)/224) + 1e-6), clip [2,5], -2
    float s = sqrtf((bx.z - bx.x) * (bx.w - bx.y));
    int lvl = (int)floorf(4.0f + log2f(s * (1.0f / 224.0f)) + 1e-6f);
    lvl = min(max(lvl, 2), 5) - 2;

    int H; float sc; const float* base;
    switch (lvl) {
        case 0:  H = 200; sc = 0.25f;    base = f0; break;
        case 1:  H = 100; sc = 0.125f;   base = f1; break;
        case 2:  H = 50;  sc = 0.0625f;  base = f2; break;
        default: H = 25;  sc = 0.03125f; base = f3; break;
    }
    const int HH = H * H;
    base += (size_t)b * 256 * HH;

    float x1s = bx.x * sc, y1s = bx.y * sc;
    float x2s = bx.z * sc, y2s = bx.w * sc;
    float binw = fmaxf(x2s - x1s, 1.0f) * (1.0f / 7.0f);
    float binh = fmaxf(y2s - y1s, 1.0f) * (1.0f / 7.0f);
    float fH = (float)H;

    // window bounds
    float ymin = y1s + 0.25f * binh, ymax = y1s + 6.75f * binh;
    float xmin = x1s + 0.25f * binw, xmax = x1s + 6.75f * binw;
    int y0  = min((int)fmaxf(ymin, 0.0f), H - 1);
    int x0  = min((int)fmaxf(xmin, 0.0f), H - 1);
    int y1m = min((int)fmaxf(fminf(ymax, fH - 1.0f), 0.0f) + 1, H - 1);
    int x1m = min((int)fmaxf(fminf(xmax, fH - 1.0f), 0.0f) + 1, H - 1);
    int hr  = y1m - y0 + 1;
    int x0d = x0 & ~1;                         // float2-aligned window start
    int wc2 = (x1m >> 1) - (x0d >> 1) + 1;     // float2 per row
    int rs2 = wc2 | 1;                         // odd float2 row stride
    const int rsF = rs2 * 2;                   // float row stride

    // per-sample bilinear params (14 y, 14 x)
    if (tid < 28) {
        bool isY = tid < 14;
        int j = isY ? tid : tid - 14;
        float o = (float)(j >> 1) + 0.25f + 0.5f * (float)(j & 1);
        float v = isY ? (y1s + o * binh) : (x1s + o * binw);
        bool valid = (v > -1.0f) && (v < fH);
        float vc = fmaxf(v, 0.0f);
        int lo = min((int)vc, H - 1);
        int hi = min(lo + 1, H - 1);
        float l = (lo >= H - 1) ? 0.0f : (vc - (float)lo);
        float h = 1.0f - l;
        if (!valid) { l = 0.0f; h = 0.0f; lo = isY ? y0 : x0d; hi = lo; }
        if (isY) { s_yl[j] = lo - y0;  s_yh[j] = hi - y0;  s_ly[j] = l; s_hy[j] = h; }
        else     { s_xl[j] = lo - x0d; s_xh[j] = hi - x0d; s_lx[j] = l; s_hx[j] = h; }
    }
    __syncthreads();

    // ---- per-thread compute params in registers (tid < 196) ----
    int cidx = 0, r0a = 0, r1a = 0, r0b = 0, r1b = 0, xl0 = 0, xh0 = 0, xl1 = 0, xh1 = 0;
    float hy0 = 0, ly0 = 0, hy1 = 0, ly1 = 0, hx0 = 0, lx0 = 0, hx1 = 0, lx1 = 0;
    if (tid < 196) {
        cidx = tid / 49;
        int bin = tid - cidx * 49;
        int oy = bin / 7, ox = bin - oy * 7;
        int j0 = oy * 2, j1 = j0 + 1, k0 = ox * 2, k1 = k0 + 1;
        r0a = s_yl[j0] * rsF; r1a = s_yh[j0] * rsF;
        r0b = s_yl[j1] * rsF; r1b = s_yh[j1] * rsF;
        xl0 = s_xl[k0]; xh0 = s_xh[k0]; xl1 = s_xl[k1]; xh1 = s_xh[k1];
        hy0 = s_hy[j0]; ly0 = s_ly[j0]; hy1 = s_hy[j1]; ly1 = s_ly[j1];
        hx0 = s_hx[k0]; lx0 = s_lx[k0]; hx1 = s_hx[k1]; lx1 = s_lx[k1];
    }
    float* outp = out + (size_t)n * 12544 + blockIdx.y * (64 * 49) + tid;

    // ---- staging lane geometry ----
    const int warp = tid >> 5, lane = tid & 31;
    const int cw = warp & 3, half = warp >> 2;   // 2 warps per channel
    const int cbase = blockIdx.y * 64;
    const bool h25 = (H == 25);
    const int wide = h25 ? (wc2 * 2) : wc2;      // elements per row (f32 / f2)
    int wp2 = 1;
    while (wp2 < wide && wp2 < 32) wp2 <<= 1;
    const int shift = __popc(wp2 - 1);
    const int rpw = 32 >> shift;                 // rows per warp step
    const int lxe = lane & (wp2 - 1);
    const int lr0 = lane >> shift;
    const int H2 = H >> 1;
    const int xlim = x1m - x0d;                  // scalar-path x predicate

    // stage chunk ck's 4 channels into buffer bf via cp.async (no reg dep)
    auto stage = [&](int bf, int ck) {
        const int cglob = cbase + ck * 4 + cw;
        uint32_t wb = (uint32_t)__cvta_generic_to_shared(&win[bf][cw][0]);
        if (!h25) {
            const float2* src = reinterpret_cast<const float2*>(base)
                              + (size_t)cglob * (HH >> 1) + y0 * H2 + (x0d >> 1);
            for (int cx0 = 0; cx0 < wc2; cx0 += wp2) {
                int xx = cx0 + lxe;
                bool inx = xx < wc2;
                for (int rb0 = half * 2 * rpw; rb0 < hr; rb0 += 4 * rpw) {
                    int ra = rb0 + lr0, rb = ra + rpw;
                    cp_async8(wb + (uint32_t)(ra * rs2 + xx) * 8u,
                              src + ra * H2 + xx, inx && ra < hr);
                    cp_async8(wb + (uint32_t)(rb * rs2 + xx) * 8u,
                              src + rb * H2 + xx, inx && rb < hr);
                }
            }
        } else {
            const float* src = base + (size_t)cglob * HH + y0 * H + x0d;
            for (int cx0 = 0; cx0 < wide; cx0 += wp2) {
                int xx = cx0 + lxe;
                bool inx = xx <= xlim;
                for (int rb0 = half * 2 * rpw; rb0 < hr; rb0 += 4 * rpw) {
                    int ra = rb0 + lr0, rb = ra + rpw;
                    cp_async4(wb + (uint32_t)(ra * rsF + xx) * 4u,
                              src + ra * H + xx, inx && ra < hr);
                    cp_async4(wb + (uint32_t)(rb * rsF + xx) * 4u,
                              src + rb * H + xx, inx && rb < hr);
                }
            }
        }
    };

    stage(0, 0);
    CP_COMMIT();

    #pragma unroll 1
    for (int ck = 0; ck < 16; ck++) {
        int bf = ck & 1;
        if (ck < 15) {
            stage(bf ^ 1, ck + 1);
            CP_COMMIT();
            CP_WAIT(1);                // buffer bf's group is complete
        } else {
            CP_WAIT(0);
        }
        __syncthreads();               // bf visible to all threads

        if (tid < 196) {
            const float* W = reinterpret_cast<const float*>(win[bf][cidx]);
            float acc =
                  hy0 * (hx0 * W[r0a + xl0] + lx0 * W[r0a + xh0])
                + ly0 * (hx0 * W[r1a + xl0] + lx0 * W[r1a + xh0])
                + hy0 * (hx1 * W[r0a + xl1] + lx1 * W[r0a + xh1])
                + ly0 * (hx1 * W[r1a + xl1] + lx1 * W[r1a + xh1])
                + hy1 * (hx0 * W[r0b + xl0] + lx0 * W[r0b + xh0])
                + ly1 * (hx0 * W[r1b + xl0] + lx0 * W[r1b + xh0])
                + hy1 * (hx1 * W[r0b + xl1] + lx1 * W[r0b + xh1])
                + ly1 * (hx1 * W[r1b + xl1] + lx1 * W[r1b + xh1]);
            outp[ck * 196] = acc * 0.25f;
        }
        __syncthreads();               // done reading bf before it's restaged
    }
}

extern "C" void kernel_launch(void* const* d_in, const int* in_sizes, int n_in,
                              void* d_out, int out_size)
{
    const float* f0 = (const float*)d_in[0];
    const float* f1 = (const float*)d_in[1];
    const float* f2 = (const float*)d_in[2];
    const float* f3 = (const float*)d_in[3];
    const float* boxes = (const float*)d_in[4];
    float* out = (float*)d_out;

    msroi_kernel<<<dim3(512, 4), 256>>>(f0, f1, f2, f3, boxes, out);
}